// round 5
// baseline (speedup 1.0000x reference)
#include <cuda_runtime.h>

#define Wd 384
#define Hd 256
#define HWD (Wd*Hd)

typedef unsigned long long ull;

// packed f32x2 ops (Blackwell sm_100+): FFMA2 / FMUL2 / pack
#define FMA2(d, a, b, c) asm("fma.rn.f32x2 %0, %1, %2, %3;" : "=l"(d) : "l"(a), "l"(b), "l"(c))
#define MUL2(d, a, b)    asm("mul.rn.f32x2 %0, %1, %2;"     : "=l"(d) : "l"(a), "l"(b))
#define ADD2(d, a, b)    asm("add.rn.f32x2 %0, %1, %2;"     : "=l"(d) : "l"(a), "l"(b))
#define PACKF2(d, lo, hi) asm("mov.b64 %0, {%1, %2};"       : "=l"(d) : "f"(lo), "f"(hi))

__device__ __forceinline__ ull ldg64(const float* p) {
    return __ldg((const ull*)p);
}

// Output: (N=2, A2=49, C=3, H, W) fp32
// Input0: low_rank (N, L=3, R=4, C=3, H, W) fp32 ; Input1: planes (N, L)
// Sampling = identity grid + constant per-(n,l,view) shift; taps/weights
// pixel-independent. Thread = (2 adjacent pixels, kq, c); pixel pair lives in
// one packed f32x2 register lane-pair throughout.
// Column interps P[0..5] (cols x-2..x+3):
//   aligned pairs Q0=(P0,P1) Q2=(P2,P3) Q4=(P4,P5); mis Q1=(P1,P2) Q3=(P3,P4)
// D-pairs: De = Q{e+1} - Qe  computed as fma(Qe, -1, Q{e+1}) (exact).

__global__ __launch_bounds__(256)
void lf2xp_kernel(const float* __restrict__ lr,
                  const float* __restrict__ planes,
                  float* __restrict__ out)
{
    const int x  = blockIdx.x * 64 + threadIdx.x * 2;   // even
    const int y  = blockIdx.y * 8  + threadIdx.y;
    const int z  = blockIdx.z;            // n*21 + kq*3 + c
    const int n  = z / 21;
    const int zc = z - n * 21;
    const int kq = zc / 3;
    const int c  = zc - kq * 3;

    const float cy = 255.0f / 512.0f;
    const float cx = 383.0f / 768.0f;

    ull NEG1, QTR;
    PACKF2(NEG1, -1.0f, -1.0f);
    PACKF2(QTR, 0.25f, 0.25f);

    const bool interior = (x >= 2) && (x <= Wd - 6);
    const int xm2 = x - 2;

    float wy_l[3], sx_l[3];
    ull wy2_l[3];
    int r0_l[3], r1_l[3];
    bool armB[3];
#pragma unroll
    for (int l = 0; l < 3; l++) {
        float p  = __ldg(planes + n * 3 + l);
        float dy = p * cy * (float)(3 - kq);
        float fy = floorf(dy);
        float wy = dy - fy;
        wy_l[l]  = wy;
        PACKF2(wy2_l[l], wy, wy);
        int iy0  = y + (int)fy;
        r0_l[l]  = min(max(iy0,     0), Hd - 1) * Wd;
        r1_l[l]  = min(max(iy0 + 1, 0), Hd - 1) * Wd;
        float s  = p * cx;
        sx_l[l]  = s;
        armB[l]  = (3.0f * s > 1.0f);
    }

    ull sum[7];
#pragma unroll
    for (int i = 0; i < 7; i++) PACKF2(sum[i], 0.0f, 0.0f);

#pragma unroll 1
    for (int r = 0; r < 4; r++) {
        ull prod[7];

#pragma unroll
        for (int l = 0; l < 3; l++) {
            const float* base = lr + (size_t)((((n * 3 + l) * 4 + r) * 3) + c) * HWD;
            const float s  = sx_l[l];
            const ull  wy2 = wy2_l[l];
            const float* q0 = base + r0_l[l];
            const float* q1 = base + r1_l[l];

            ull Q0, Q2, Q4;
            if (interior) {
                ull A0 = ldg64(q0 + xm2), A1 = ldg64(q0 + xm2 + 2), A2 = ldg64(q0 + xm2 + 4);
                ull B0 = ldg64(q1 + xm2), B1 = ldg64(q1 + xm2 + 2), B2 = ldg64(q1 + xm2 + 4);
                ull t0, t1, t2;
                FMA2(t0, A0, NEG1, B0);  FMA2(Q0, wy2, t0, A0);
                FMA2(t1, A1, NEG1, B1);  FMA2(Q2, wy2, t1, A1);
                FMA2(t2, A2, NEG1, B2);  FMA2(Q4, wy2, t2, A2);
            } else {
                const float wy = wy_l[l];
                float P[6];
#pragma unroll
                for (int d = 0; d < 6; d++) {
                    int col = min(max(xm2 + d, 0), Wd - 1);
                    float a = __ldg(q0 + col), b = __ldg(q1 + col);
                    P[d] = fmaf(wy, b - a, a);
                }
                PACKF2(Q0, P[0], P[1]);
                PACKF2(Q2, P[2], P[3]);
                PACKF2(Q4, P[4], P[5]);
            }

            // misaligned pairs
            float2 f0 = *(float2*)&Q0;
            float2 f2 = *(float2*)&Q2;
            float2 f4 = *(float2*)&Q4;
            ull Q1, Q3;
            PACKF2(Q1, f0.y, f2.x);
            PACKF2(Q3, f2.y, f4.x);

            ull v[7];
            if (!armB[l]) {
                // pattern A: v0-2 -> (Q2, D=Q3-Q2); v3 -> Q2; v4-6 -> (Q1, D=Q2-Q1)
                ull DA, DB;
                FMA2(DA, Q2, NEG1, Q3);
                FMA2(DB, Q1, NEG1, Q2);
                const float w0 = 3.f*s, w1 = 2.f*s, w2 = s;
                const float w4 = 1.f - s, w5 = 1.f - 2.f*s, w6 = 1.f - 3.f*s;
                ull w0p, w1p, w2p, w4p, w5p, w6p;
                PACKF2(w0p, w0, w0); PACKF2(w1p, w1, w1); PACKF2(w2p, w2, w2);
                PACKF2(w4p, w4, w4); PACKF2(w5p, w5, w5); PACKF2(w6p, w6, w6);
                FMA2(v[0], w0p, DA, Q2);
                FMA2(v[1], w1p, DA, Q2);
                FMA2(v[2], w2p, DA, Q2);
                v[3] = Q2;
                FMA2(v[4], w4p, DB, Q1);
                FMA2(v[5], w5p, DB, Q1);
                FMA2(v[6], w6p, DB, Q1);
            } else {
                // pattern B: v0 -> (Q3, D=Q4-Q3); v1-2 -> (Q2, D=Q3-Q2); v3 -> Q2;
                //            v4-5 -> (Q1, D=Q2-Q1); v6 -> (Q0, D=Q1-Q0)
                ull DC, DA, DB, DD;
                FMA2(DC, Q3, NEG1, Q4);
                FMA2(DA, Q2, NEG1, Q3);
                FMA2(DB, Q1, NEG1, Q2);
                FMA2(DD, Q0, NEG1, Q1);
                const float w0 = 3.f*s - 1.f, w1 = 2.f*s, w2 = s;
                const float w4 = 1.f - s, w5 = 1.f - 2.f*s, w6 = 2.f - 3.f*s;
                ull w0p, w1p, w2p, w4p, w5p, w6p;
                PACKF2(w0p, w0, w0); PACKF2(w1p, w1, w1); PACKF2(w2p, w2, w2);
                PACKF2(w4p, w4, w4); PACKF2(w5p, w5, w5); PACKF2(w6p, w6, w6);
                FMA2(v[0], w0p, DC, Q3);
                FMA2(v[1], w1p, DA, Q2);
                FMA2(v[2], w2p, DA, Q2);
                v[3] = Q2;
                FMA2(v[4], w4p, DB, Q1);
                FMA2(v[5], w5p, DB, Q1);
                FMA2(v[6], w6p, DD, Q0);
            }

            if (l == 0) {
#pragma unroll
                for (int i = 0; i < 7; i++) prod[i] = v[i];
            } else {
#pragma unroll
                for (int i = 0; i < 7; i++) MUL2(prod[i], prod[i], v[i]);
            }
        }
#pragma unroll
        for (int i = 0; i < 7; i++) ADD2(sum[i], sum[i], prod[i]);
    }

    // write (N, A2, C, H, W); a = kq*7 + lq ; packed pair -> STG.64
    float* o = out + ((size_t)((n * 49 + kq * 7) * 3 + c)) * HWD + y * Wd + x;
#pragma unroll
    for (int lq = 0; lq < 7; lq++) {
        ull res;
        MUL2(res, sum[lq], QTR);
        *(ull*)(o + (size_t)lq * 3 * HWD) = res;
    }
}

extern "C" void kernel_launch(void* const* d_in, const int* in_sizes, int n_in,
                              void* d_out, int out_size)
{
    const float* low_rank = (const float*)d_in[0];
    const float* planes   = (const float*)d_in[1];
    float* out = (float*)d_out;

    dim3 block(32, 8, 1);
    dim3 grid(Wd / 64, Hd / 8, 42);   // z = n*21 + kq*3 + c, N=2
    lf2xp_kernel<<<grid, block>>>(low_rank, planes, out);
}

// round 6
// speedup vs baseline: 1.1755x; 1.1755x over previous
#include <cuda_runtime.h>

#define Wd 384
#define Hd 256
#define HWD (Wd*Hd)

// Output: (N=2, A2=49, C=3, H, W) fp32
// Input0: low_rank (N, L=3, R=4, C=3, H, W) fp32 ; Input1: planes (N, L)
//
// Sampling = identity grid + constant per-(n,l,view) shift:
//   dx = p*cx*(3-lq), cx=383/768 ; dy = p*cy*(3-kq), cy=255/512
// Taps/weights pixel-independent; borders via clamped load addresses.
// Lane i owns pixels (x, x+1), x = 64*bx + 2*lane. It loads/interps ONLY its
// own column pair; neighbor column interps come from __shfl (dedups the 3x
// column redundancy of the naive version). Lanes 0/31 fetch their overhang
// pair via a predicated clamped path.

__global__ __launch_bounds__(256)
void lfsh_kernel(const float* __restrict__ lr,
                 const float* __restrict__ planes,
                 float* __restrict__ out)
{
    const int lane = threadIdx.x;              // 0..31
    const int XB = blockIdx.x * 64;
    const int x  = XB + lane * 2;              // even
    const int y  = blockIdx.y * 8 + threadIdx.y;
    const int z  = blockIdx.z;                 // n*21 + kq*3 + c
    const int n  = z / 21;
    const int zc = z - n * 21;
    const int kq = zc / 3;
    const int c  = zc - kq * 3;

    const float cy = 255.0f / 512.0f;
    const float cx = 383.0f / 768.0f;

    const bool isL = (lane == 0), isR = (lane == 31);
    const bool edge = isL || isR;
    const int eb  = isR ? (XB + 64) : (XB - 2);
    const int ec0 = min(max(eb,     0), Wd - 1);
    const int ec1 = min(max(eb + 1, 0), Wd - 1);

    float wy_l[3], s_l[3];
    const float* q0p[3];
    const float* q1p[3];
    bool armB[3];
#pragma unroll
    for (int l = 0; l < 3; l++) {
        float p   = __ldg(planes + n * 3 + l);
        float dyv = p * cy * (float)(3 - kq);
        float fy  = floorf(dyv);
        wy_l[l]   = dyv - fy;
        int iy0   = y + (int)fy;
        int r0    = min(max(iy0,     0), Hd - 1) * Wd;
        int r1    = min(max(iy0 + 1, 0), Hd - 1) * Wd;
        const float* base = lr + (size_t)((n * 3 + l) * 12 + c) * HWD;
        q0p[l] = base + r0;
        q1p[l] = base + r1;
        float s = p * cx;
        s_l[l]  = s;
        armB[l] = (3.0f * s > 1.0f);
    }

    float sum0[7], sum1[7];
#pragma unroll
    for (int i = 0; i < 7; i++) { sum0[i] = 0.0f; sum1[i] = 0.0f; }

#pragma unroll 1
    for (int r = 0; r < 4; r++) {
        const int roff = r * (3 * HWD);

        // own-pair loads, all 3 layers batched (MLP=6)
        float2 A[3], Bv[3];
#pragma unroll
        for (int l = 0; l < 3; l++) {
            A[l]  = __ldg((const float2*)(q0p[l] + roff + x));
            Bv[l] = __ldg((const float2*)(q1p[l] + roff + x));
        }

        // edge overhang pair (lanes 0/31 only), clamped columns
        float eP0[3], eP1[3];
        if (edge) {
#pragma unroll
            for (int l = 0; l < 3; l++) {
                const float* qq0 = q0p[l] + roff;
                const float* qq1 = q1p[l] + roff;
                float a0 = __ldg(qq0 + ec0), b0 = __ldg(qq1 + ec0);
                float a1 = __ldg(qq0 + ec1), b1 = __ldg(qq1 + ec1);
                eP0[l] = fmaf(wy_l[l], b0 - a0, a0);
                eP1[l] = fmaf(wy_l[l], b1 - a1, a1);
            }
        }

        float p0[7], p1[7];
#pragma unroll
        for (int l = 0; l < 3; l++) {
            const float wy = wy_l[l];
            const float s  = s_l[l];

            // own column interps (cols x, x+1)
            float P2 = fmaf(wy, Bv[l].x - A[l].x, A[l].x);
            float P3 = fmaf(wy, Bv[l].y - A[l].y, A[l].y);

            // neighbor interps via shuffle (bitwise same values)
            float Pm1 = __shfl_up_sync(0xffffffffu, P3, 1);    // col x-1
            float Pm2 = __shfl_up_sync(0xffffffffu, P2, 1);    // col x-2
            float Pp2 = __shfl_down_sync(0xffffffffu, P2, 1);  // col x+2
            float Pp3 = __shfl_down_sync(0xffffffffu, P3, 1);  // col x+3
            if (isL) { Pm2 = eP0[l]; Pm1 = eP1[l]; }
            if (isR) { Pp2 = eP0[l]; Pp3 = eP1[l]; }

            // P[0..5] = {Pm2, Pm1, P2, P3, Pp2, Pp3}
            float D1 = P2  - Pm1;
            float D2 = P3  - P2;
            float D3 = Pp2 - P3;

            float va[7], vb[7];
            if (!armB[l]) {
                // pattern A: left-tap offsets {2,2,2,2,1,1,1}
                const float w0 = 3.f*s, w1 = 2.f*s, w2 = s;
                const float w4 = 1.f - s, w5 = 1.f - 2.f*s, w6 = 1.f - 3.f*s;
                va[0] = fmaf(w0, D2, P2);
                va[1] = fmaf(w1, D2, P2);
                va[2] = fmaf(w2, D2, P2);
                va[3] = P2;
                va[4] = fmaf(w4, D1, Pm1);
                va[5] = fmaf(w5, D1, Pm1);
                va[6] = fmaf(w6, D1, Pm1);
                vb[0] = fmaf(w0, D3, P3);
                vb[1] = fmaf(w1, D3, P3);
                vb[2] = fmaf(w2, D3, P3);
                vb[3] = P3;
                vb[4] = fmaf(w4, D2, P2);
                vb[5] = fmaf(w5, D2, P2);
                vb[6] = fmaf(w6, D2, P2);
            } else {
                // pattern B: left-tap offsets {3,2,2,2,1,1,0}
                const float w0 = 3.f*s - 1.f, w1 = 2.f*s, w2 = s;
                const float w4 = 1.f - s, w5 = 1.f - 2.f*s, w6 = 2.f - 3.f*s;
                float D0 = Pm1 - Pm2;
                float D4 = Pp3 - Pp2;
                va[0] = fmaf(w0, D3, P3);
                va[1] = fmaf(w1, D2, P2);
                va[2] = fmaf(w2, D2, P2);
                va[3] = P2;
                va[4] = fmaf(w4, D1, Pm1);
                va[5] = fmaf(w5, D1, Pm1);
                va[6] = fmaf(w6, D0, Pm2);
                vb[0] = fmaf(w0, D4, Pp2);
                vb[1] = fmaf(w1, D3, P3);
                vb[2] = fmaf(w2, D3, P3);
                vb[3] = P3;
                vb[4] = fmaf(w4, D2, P2);
                vb[5] = fmaf(w5, D2, P2);
                vb[6] = fmaf(w6, D1, Pm1);
            }

            if (l == 0) {
#pragma unroll
                for (int i = 0; i < 7; i++) { p0[i] = va[i]; p1[i] = vb[i]; }
            } else if (l == 1) {
#pragma unroll
                for (int i = 0; i < 7; i++) { p0[i] *= va[i]; p1[i] *= vb[i]; }
            } else {
#pragma unroll
                for (int i = 0; i < 7; i++) {
                    sum0[i] = fmaf(p0[i], va[i], sum0[i]);
                    sum1[i] = fmaf(p1[i], vb[i], sum1[i]);
                }
            }
        }
    }

    // write (N, A2, C, H, W); a = kq*7 + lq ; adjacent pixel pair -> STG.64
    float* o = out + ((size_t)((n * 49 + kq * 7) * 3 + c)) * HWD + y * Wd + x;
#pragma unroll
    for (int lq = 0; lq < 7; lq++) {
        float2 v = make_float2(sum0[lq] * 0.25f, sum1[lq] * 0.25f);
        *(float2*)(o + (size_t)lq * 3 * HWD) = v;
    }
}

extern "C" void kernel_launch(void* const* d_in, const int* in_sizes, int n_in,
                              void* d_out, int out_size)
{
    const float* low_rank = (const float*)d_in[0];
    const float* planes   = (const float*)d_in[1];
    float* out = (float*)d_out;

    dim3 block(32, 8, 1);
    dim3 grid(Wd / 64, Hd / 8, 42);   // z = n*21 + kq*3 + c, N=2
    lfsh_kernel<<<grid, block>>>(low_rank, planes, out);
}